// round 15
// baseline (speedup 1.0000x reference)
#include <cuda_runtime.h>
#include <cuda_fp16.h>
#include <cstdint>

// ---------------- Problem constants ----------------
#define B_TOTAL   8192
#define F_DIM     64
#define NX        82
#define NY        67
#define NYP       96
#define P_TOTAL   (NX * NY)      // 5494
#define KP        64             // fp16 K
#define KSTEPS    (KP / 16)      // 4

// ---------------- Tile config ----------------
#define TILE_M    128
#define BT_PER_CTA 4
#define GRID_Y    (B_TOTAL / TILE_M / BT_PER_CTA)   // 16
#define ROWE      72             // W smem row stride in fp16 (144B)

// SMEM layout (bytes)
#define A_TILE_BYTES 16384                  // 128x64 fp16 in fragment order
#define OFF_A0    0
#define OFF_A1    A_TILE_BYTES              // 16384
#define OFF_W     OFF_A1                    // W prologue image overlays A1 (A1 written later)
#define OFF_BIAS  (2 * A_TILE_BYTES)        // 32768
#define SMEM_TOTAL (OFF_BIAS + 384)         // 33152

// ---------------- Scratch (device globals; no allocation allowed) ----------------
// A in mma fragment order: [g32][ks][mf][lane] of uint4, g32 = 32-row group
#define AFRAG_U4  (B_TOTAL * KP * 2 / 16)   // 65536 uint4
__device__ __align__(16) uint4 g_Afrag[AFRAG_U4];
__device__ __align__(16) __half g_Wp[NX * NYP * KP];   // [x][96][64]

static __device__ __forceinline__ uint32_t smem_u32(const void* p) {
    return (uint32_t)__cvta_generic_to_shared(p);
}
static __device__ __forceinline__ void cp_async16(uint32_t dst, const void* src) {
    asm volatile("cp.async.cg.shared.global [%0], [%1], 16;" :: "r"(dst), "l"(src));
}
static __device__ __forceinline__ uint32_t packh2(float a, float b) {
    __half2 h = __floats2half2_rn(a, b);
    return *(uint32_t*)&h;
}

// ---------------- Merged prep kernel (layout unchanged) ----------------
#define W_CHUNKS (NX * NYP * 16)                 // 125952
#define PREP_THREADS (AFRAG_U4 + W_CHUNKS)       // 191488
#define PREP_BLOCKS ((PREP_THREADS + 255) / 256) // 749
__global__ void prep_kernel(const float* __restrict__ in, const float* __restrict__ W) {
    int idx = blockIdx.x * 256 + threadIdx.x;
    if (idx < AFRAG_U4) {
        int lane = idx & 31;
        int rest = idx >> 5;
        int mf = rest & 1;
        int ks = (rest >> 1) & 3;
        int g32 = rest >> 3;
        int b0 = g32 * 32 + mf * 16 + (lane >> 2);
        int k0 = ks * 16 + (lane & 3) * 2;
        const float* p = in + b0 * F_DIM + k0;
        float2 v0 = *(const float2*)p;
        float2 v1 = *(const float2*)(p + 8 * F_DIM);
        float2 v2 = *(const float2*)(p + 8);
        float2 v3 = *(const float2*)(p + 8 * F_DIM + 8);
        uint4 o;
        o.x = packh2(v0.x, v0.y);
        o.y = packh2(v1.x, v1.y);
        o.z = packh2(v2.x, v2.y);
        o.w = packh2(v3.x, v3.y);
        g_Afrag[idx] = o;
    } else if (idx < PREP_THREADS) {
        int j = idx - AFRAG_U4;
        int x = j / (NYP * 16);
        int rem = j - x * (NYP * 16);
        int y = rem >> 4;
        int c4 = rem & 15;
        uint2 pack = {0u, 0u};
        if (y < NY) {
            float4 v = *(const float4*)(W + ((size_t)(y * NX + x) * F_DIM + c4 * 4));
            pack.x = packh2(v.x, v.y);
            pack.y = packh2(v.z, v.w);
        }
        *(uint2*)(g_Wp + ((size_t)(x * NYP + y) * KP + c4 * 4)) = pack;
    }
}

// ---------------- GEMM kernel ----------------
// Grid: (x = 0..81, by = 0..15). Block: 256 threads (8 warps, 4M x 2N).
// W register-resident; A cp.async double buffer; DIRECT bias-folded writeout
// from accumulators (no smem staging). STG.64 when x even; STG.32 pairs when
// x odd (x*67 element offset is odd -> 8B stores would be misaligned).
__global__ __launch_bounds__(256, 2)
void gemm_kernel(const float* __restrict__ bias, float* __restrict__ out) {
    extern __shared__ __align__(16) char smem[];
    float* bias_s = (float*)(smem + OFF_BIAS);   // [96], zero-padded

    const int x  = blockIdx.x;
    const int by = blockIdx.y;
    const int tid = threadIdx.x;
    const int lane = tid & 31;
    const int warp = tid >> 5;
    const int warpM = warp & 3;   // 0..3
    const int warpN = warp >> 2;  // 0..1
    const uint32_t sbase = smem_u32(smem);

    // ---- Prologue: W tile + A[0] via one cp.async group ----
    {
        const char* srcW = (const char*)(g_Wp + (size_t)x * NYP * KP);
        #pragma unroll
        for (int i = tid; i < NYP * 8; i += 256) {
            int r = i >> 3;
            int c = i & 7;
            cp_async16(sbase + OFF_W + r * 144 + c * 16, srcW + r * 128 + c * 16);
        }
        const char* srcA = (const char*)(g_Afrag + ((size_t)(by * BT_PER_CTA * 4) << 8));
        #pragma unroll
        for (int i = tid; i < A_TILE_BYTES / 16; i += 256)   // 1024 chunks
            cp_async16(sbase + OFF_A0 + i * 16, srcA + i * 16);
        asm volatile("cp.async.commit_group;" ::: "memory");
    }
    if (tid < NYP) bias_s[tid] = (tid < NY) ? bias[tid * NX + x] : 0.0f;
    asm volatile("cp.async.wait_group 0;" ::: "memory");
    __syncthreads();

    // ---- Hoist W fragments to registers (once) ----
    uint32_t wreg[KSTEPS][3][4];
    {
        const uint32_t b_base = sbase + OFF_W
            + ((warpN * 48 + (lane & 15)) * ROWE + (lane >> 4) * 8) * 2;
        const uint32_t NG_STRIDE = 16 * ROWE * 2;
        #pragma unroll
        for (int ks = 0; ks < KSTEPS; ks++) {
            #pragma unroll
            for (int g = 0; g < 3; g++) {
                asm volatile("ldmatrix.sync.aligned.m8n8.x4.shared.b16 {%0,%1,%2,%3}, [%4];"
                             : "=r"(wreg[ks][g][0]), "=r"(wreg[ks][g][1]),
                               "=r"(wreg[ks][g][2]), "=r"(wreg[ks][g][3])
                             : "r"(b_base + g * NG_STRIDE + ks * 32));
            }
        }
    }
    __syncthreads();   // W smem image (over A1) dead; A1 prefetch may start

    // d-frag output coordinates
    const int r0 = warpM * 32 + (lane >> 2);      // row within tile
    const int cb = warpN * 48 + (lane & 3) * 2;   // y base (even)
    const bool xEven = ((x & 1) == 0);

    // bias pairs for this thread's 6 column groups (loaded once; regs)
    float bv0[6], bv1[6];
    #pragma unroll
    for (int nf = 0; nf < 6; nf++) {
        bv0[nf] = bias_s[cb + nf * 8];
        bv1[nf] = bias_s[cb + nf * 8 + 1];
    }

    // per-thread A-fragment smem base: warpM group of 4KB, lane slot of 16B
    const uint32_t aOffBase = (uint32_t)(warpM * 4096 + lane * 16);

    #pragma unroll
    for (int t = 0; t < BT_PER_CTA; t++) {
        const int bt = by * BT_PER_CTA + t;
        const uint32_t aBuf = sbase + ((t & 1) ? OFF_A1 : OFF_A0) + aOffBase;

        // ---- Prefetch A[t+1] into the other buffer ----
        if (t + 1 < BT_PER_CTA) {
            const char* srcA = (const char*)(g_Afrag + ((size_t)((bt + 1) * 4) << 8));
            const uint32_t dst = sbase + ((t & 1) ? OFF_A0 : OFF_A1);
            #pragma unroll
            for (int i = tid; i < A_TILE_BYTES / 16; i += 256)
                cp_async16(dst + i * 16, srcA + i * 16);
            asm volatile("cp.async.commit_group;" ::: "memory");
        }

        float d[2][6][4];
        #pragma unroll
        for (int mf = 0; mf < 2; mf++)
            #pragma unroll
            for (int nf = 0; nf < 6; nf++)
                #pragma unroll
                for (int j = 0; j < 4; j++) d[mf][nf][j] = 0.0f;

        #pragma unroll
        for (int ks = 0; ks < KSTEPS; ks++) {
            uint4 a0, a1;
            asm volatile("ld.shared.v4.b32 {%0,%1,%2,%3}, [%4];"
                         : "=r"(a0.x), "=r"(a0.y), "=r"(a0.z), "=r"(a0.w)
                         : "r"(aBuf + (ks * 2 + 0) * 512));
            asm volatile("ld.shared.v4.b32 {%0,%1,%2,%3}, [%4];"
                         : "=r"(a1.x), "=r"(a1.y), "=r"(a1.z), "=r"(a1.w)
                         : "r"(aBuf + (ks * 2 + 1) * 512));
            const uint32_t* am[2] = { (const uint32_t*)&a0, (const uint32_t*)&a1 };
            #pragma unroll
            for (int mf = 0; mf < 2; mf++) {
                #pragma unroll
                for (int g = 0; g < 3; g++) {
                    #pragma unroll
                    for (int h = 0; h < 2; h++) {
                        float* dd = d[mf][g * 2 + h];
                        asm volatile(
                            "mma.sync.aligned.m16n8k16.row.col.f32.f16.f16.f32 "
                            "{%0,%1,%2,%3}, {%4,%5,%6,%7}, {%8,%9}, {%0,%1,%2,%3};"
                            : "+f"(dd[0]), "+f"(dd[1]), "+f"(dd[2]), "+f"(dd[3])
                            : "r"(am[mf][0]), "r"(am[mf][1]), "r"(am[mf][2]), "r"(am[mf][3]),
                              "r"(wreg[ks][g][h]), "r"(wreg[ks][g][2 + h]));
                    }
                }
            }
        }

        // ---- Direct writeout: bias-folded stores from fragments ----
        // Element offset = row*5494 + x*67 + y. For even x: 8B-aligned float2
        // stores. For odd x: x*67 is odd -> scalar stores (still coalesced).
        {
            float* pRow = out + (size_t)(bt * TILE_M + r0) * P_TOTAL + x * NY;
            #pragma unroll
            for (int mf = 0; mf < 2; mf++) {
                float* pA = pRow + (size_t)(mf * 16) * P_TOTAL;
                float* pB = pA + (size_t)8 * P_TOTAL;
                if (xEven) {
                    #pragma unroll
                    for (int nf = 0; nf < 6; nf++) {
                        const int y = cb + nf * 8;   // even
                        if (y + 1 < NY) {
                            *(float2*)(pA + y) = make_float2(d[mf][nf][0] + bv0[nf],
                                                             d[mf][nf][1] + bv1[nf]);
                            *(float2*)(pB + y) = make_float2(d[mf][nf][2] + bv0[nf],
                                                             d[mf][nf][3] + bv1[nf]);
                        } else if (y < NY) {
                            pA[y] = d[mf][nf][0] + bv0[nf];
                            pB[y] = d[mf][nf][2] + bv0[nf];
                        }
                    }
                } else {
                    #pragma unroll
                    for (int nf = 0; nf < 6; nf++) {
                        const int y = cb + nf * 8;   // even
                        if (y + 1 < NY) {
                            pA[y]     = d[mf][nf][0] + bv0[nf];
                            pA[y + 1] = d[mf][nf][1] + bv1[nf];
                            pB[y]     = d[mf][nf][2] + bv0[nf];
                            pB[y + 1] = d[mf][nf][3] + bv1[nf];
                        } else if (y < NY) {
                            pA[y] = d[mf][nf][0] + bv0[nf];
                            pB[y] = d[mf][nf][2] + bv0[nf];
                        }
                    }
                }
            }
        }

        // ---- Close pipeline stage: A[t+1] landed; buffer handoff ----
        asm volatile("cp.async.wait_group 0;" ::: "memory");
        __syncthreads();
    }
}

// ---------------- Launch ----------------
extern "C" void kernel_launch(void* const* d_in, const int* in_sizes, int n_in,
                              void* d_out, int out_size) {
    const float* inputs = nullptr;  // 8192*64
    const float* W = nullptr;       // 5494*64
    const float* bias = nullptr;    // 5494
    for (int i = 0; i < n_in; i++) {
        if (in_sizes[i] == B_TOTAL * F_DIM) inputs = (const float*)d_in[i];
        else if (in_sizes[i] == P_TOTAL * F_DIM) W = (const float*)d_in[i];
        else if (in_sizes[i] == P_TOTAL) bias = (const float*)d_in[i];
    }
    float* out = (float*)d_out;

    prep_kernel<<<PREP_BLOCKS, 256>>>(inputs, W);

    cudaFuncSetAttribute(gemm_kernel, cudaFuncAttributeMaxDynamicSharedMemorySize, SMEM_TOTAL);
    dim3 grid(NX, GRID_Y);   // (82, 16)
    gemm_kernel<<<grid, 256, SMEM_TOTAL>>>(bias, out);
}

// round 16
// speedup vs baseline: 1.5222x; 1.5222x over previous
#include <cuda_runtime.h>
#include <cuda_fp16.h>
#include <cstdint>

// ---------------- Problem constants ----------------
#define B_TOTAL   8192
#define F_DIM     64
#define NX        82
#define NY        67
#define NYP       96
#define P_TOTAL   (NX * NY)      // 5494
#define KP        64             // fp16 K
#define KSTEPS    (KP / 16)      // 4

// ---------------- Tile config (round-12 shape) ----------------
#define TILE_M    128
#define BT_PER_CTA 4
#define GRID_Y    (B_TOTAL / TILE_M / BT_PER_CTA)   // 16
#define ROWE      72             // W smem row stride in fp16 (144B)

// SMEM layout (bytes)
#define A_TILE_BYTES 16384                  // 128x64 fp16 in fragment order
#define OFF_A0    0
#define OFF_A1    A_TILE_BYTES              // 16384
#define OFF_DS    (2 * A_TILE_BYTES)        // 32768
#define DS_STRIDE 68
#define DS_BYTES  (TILE_M * DS_STRIDE * 4)  // 34816
#define OFF_BIAS  (OFF_DS + DS_BYTES)       // 67584
#define OFF_W     OFF_DS                    // W prologue image overlays Ds (dead after hoist)
#define SMEM_TOTAL (OFF_BIAS + 384)         // 67968 -> 2 CTAs/SM

// ---------------- Scratch (device globals; no allocation allowed) ----------------
// A in mma fragment order: [g32][ks][mf][lane] of uint4, g32 = 32-row group
#define AFRAG_U4  (B_TOTAL * KP * 2 / 16)   // 65536 uint4
__device__ __align__(16) uint4 g_Afrag[AFRAG_U4];

static __device__ __forceinline__ uint32_t smem_u32(const void* p) {
    return (uint32_t)__cvta_generic_to_shared(p);
}
static __device__ __forceinline__ void cp_async16(uint32_t dst, const void* src) {
    asm volatile("cp.async.cg.shared.global [%0], [%1], 16;" :: "r"(dst), "l"(src));
}
static __device__ __forceinline__ uint32_t packh2(float a, float b) {
    __half2 h = __floats2half2_rn(a, b);
    return *(uint32_t*)&h;
}

// ---------------- Prep kernel: A fragments only ----------------
#define PREP_BLOCKS (AFRAG_U4 / 256)   // 256
__global__ void prep_kernel(const float* __restrict__ in) {
    int idx = blockIdx.x * 256 + threadIdx.x;
    // decompose: [g32][ks(2)][mf(1)][lane(5)]
    int lane = idx & 31;
    int rest = idx >> 5;
    int mf = rest & 1;
    int ks = (rest >> 1) & 3;
    int g32 = rest >> 3;
    int b0 = g32 * 32 + mf * 16 + (lane >> 2);
    int k0 = ks * 16 + (lane & 3) * 2;
    const float* p = in + b0 * F_DIM + k0;
    float2 v0 = *(const float2*)p;                   // a0: (b0,   k0)
    float2 v1 = *(const float2*)(p + 8 * F_DIM);     // a1: (b0+8, k0)
    float2 v2 = *(const float2*)(p + 8);             // a2: (b0,   k0+8)
    float2 v3 = *(const float2*)(p + 8 * F_DIM + 8); // a3: (b0+8, k0+8)
    uint4 o;
    o.x = packh2(v0.x, v0.y);
    o.y = packh2(v1.x, v1.y);
    o.z = packh2(v2.x, v2.y);
    o.w = packh2(v3.x, v3.y);
    g_Afrag[idx] = o;
}

// ---------------- GEMM kernel ----------------
// Grid: (x = 0..81, by = 0..15). Block: 256 threads (8 warps, 4M x 2N).
// W loaded from gmem f32 in-prologue -> fp16 smem -> registers; A cp.async
// double buffer; tile t's MMA overlapped with tile t-1's staged writeout.
__global__ __launch_bounds__(256, 2)
void gemm_kernel(const float* __restrict__ Wg, const float* __restrict__ bias,
                 float* __restrict__ out) {
    extern __shared__ __align__(16) char smem[];
    float* Ds = (float*)(smem + OFF_DS);         // [128][68] staging
    float* bias_s = (float*)(smem + OFF_BIAS);   // [96], zero-padded

    const int x  = blockIdx.x;
    const int by = blockIdx.y;
    const int tid = threadIdx.x;
    const int lane = tid & 31;
    const int warp = tid >> 5;
    const int warpM = warp & 3;   // 0..3
    const int warpN = warp >> 2;  // 0..1
    const uint32_t sbase = smem_u32(smem);

    // ---- Prologue: A[0] via cp.async (in flight during W conversion) ----
    {
        const char* srcA = (const char*)(g_Afrag + ((size_t)(by * BT_PER_CTA * 4) << 8));
        #pragma unroll
        for (int i = tid; i < A_TILE_BYTES / 16; i += 256)   // 1024 chunks
            cp_async16(sbase + OFF_A0 + i * 16, srcA + i * 16);
        asm volatile("cp.async.commit_group;" ::: "memory");
    }
    // ---- W column x: gmem f32 -> fp16 smem image [96][ROWE] (fused prep) ----
    {
        // zero padding rows 67..95 (disjoint from fill region; no race)
        for (int i = tid; i < (NYP - NY) * (ROWE / 8); i += 256) {   // 29*9=261 float4
            int r = NY + i / (ROWE / 8);
            int c = i % (ROWE / 8);
            *(uint4*)(smem + OFF_W + r * 144 + c * 16) = make_uint4(0, 0, 0, 0);
        }
        // fill rows 0..66: row*256B f32, each lane a float2 -> half2 STS.32
        for (int i = tid; i < NY * 32; i += 256) {   // 2144
            int r = i >> 5;
            int c2 = i & 31;
            float2 v = *(const float2*)(Wg + ((size_t)(r * NX + x) * F_DIM + c2 * 2));
            uint32_t h = packh2(v.x, v.y);
            *(uint32_t*)(smem + OFF_W + r * 144 + c2 * 4) = h;
        }
    }
    if (tid < NYP) bias_s[tid] = (tid < NY) ? bias[tid * NX + x] : 0.0f;
    asm volatile("cp.async.wait_group 0;" ::: "memory");
    __syncthreads();

    // ---- Hoist W fragments to registers (once) ----
    uint32_t wreg[KSTEPS][3][4];
    {
        const uint32_t b_base = sbase + OFF_W
            + ((warpN * 48 + (lane & 15)) * ROWE + (lane >> 4) * 8) * 2;
        const uint32_t NG_STRIDE = 16 * ROWE * 2;
        #pragma unroll
        for (int ks = 0; ks < KSTEPS; ks++) {
            #pragma unroll
            for (int g = 0; g < 3; g++) {
                asm volatile("ldmatrix.sync.aligned.m8n8.x4.shared.b16 {%0,%1,%2,%3}, [%4];"
                             : "=r"(wreg[ks][g][0]), "=r"(wreg[ks][g][1]),
                               "=r"(wreg[ks][g][2]), "=r"(wreg[ks][g][3])
                             : "r"(b_base + g * NG_STRIDE + ks * 32));
            }
        }
    }
    __syncthreads();   // W smem image dead; Ds may be overwritten from here on

    // d-frag output coordinates
    const int r0 = warpM * 32 + (lane >> 2);
    const int cb = warpN * 48 + (lane & 3) * 2;

    // per-thread A-fragment smem base: warpM group of 4KB, lane slot of 16B
    const uint32_t aOffBase = (uint32_t)(warpM * 4096 + lane * 16);

    #pragma unroll
    for (int t = 0; t < BT_PER_CTA; t++) {
        const int bt = by * BT_PER_CTA + t;
        const uint32_t aBuf = sbase + ((t & 1) ? OFF_A1 : OFF_A0) + aOffBase;

        // ---- Prefetch A[t+1] (buffer free: all warps passed compute(t-1) + 2 bars) ----
        if (t + 1 < BT_PER_CTA) {
            const char* srcA = (const char*)(g_Afrag + ((size_t)((bt + 1) * 4) << 8));
            const uint32_t dst = sbase + ((t & 1) ? OFF_A0 : OFF_A1);
            #pragma unroll
            for (int i = tid; i < A_TILE_BYTES / 16; i += 256)
                cp_async16(dst + i * 16, srcA + i * 16);
            asm volatile("cp.async.commit_group;" ::: "memory");
        }

        float d[2][6][4];
        #pragma unroll
        for (int mf = 0; mf < 2; mf++)
            #pragma unroll
            for (int nf = 0; nf < 6; nf++)
                #pragma unroll
                for (int j = 0; j < 4; j++) d[mf][nf][j] = 0.0f;

        // previous tile's writeout walkers (valid when t > 0)
        float* gRowW = out + ((size_t)((bt - 1) * TILE_M + warp * 16)) * P_TOTAL + x * NY + lane;
        const float* sRowW = Ds + (warp * 16) * DS_STRIDE + lane;

        // ---- Merged window: compute d(t) interleaved with writeout(t-1) ----
        #pragma unroll
        for (int ks = 0; ks < KSTEPS; ks++) {
            uint4 a0, a1;
            asm volatile("ld.shared.v4.b32 {%0,%1,%2,%3}, [%4];"
                         : "=r"(a0.x), "=r"(a0.y), "=r"(a0.z), "=r"(a0.w)
                         : "r"(aBuf + (ks * 2 + 0) * 512));
            asm volatile("ld.shared.v4.b32 {%0,%1,%2,%3}, [%4];"
                         : "=r"(a1.x), "=r"(a1.y), "=r"(a1.z), "=r"(a1.w)
                         : "r"(aBuf + (ks * 2 + 1) * 512));
            const uint32_t* am[2] = { (const uint32_t*)&a0, (const uint32_t*)&a1 };
            #pragma unroll
            for (int mf = 0; mf < 2; mf++) {
                #pragma unroll
                for (int g = 0; g < 3; g++) {
                    #pragma unroll
                    for (int h = 0; h < 2; h++) {
                        float* dd = d[mf][g * 2 + h];
                        asm volatile(
                            "mma.sync.aligned.m16n8k16.row.col.f32.f16.f16.f32 "
                            "{%0,%1,%2,%3}, {%4,%5,%6,%7}, {%8,%9}, {%0,%1,%2,%3};"
                            : "+f"(dd[0]), "+f"(dd[1]), "+f"(dd[2]), "+f"(dd[3])
                            : "r"(am[mf][0]), "r"(am[mf][1]), "r"(am[mf][2]), "r"(am[mf][3]),
                              "r"(wreg[ks][g][h]), "r"(wreg[ks][g][2 + h]));
                    }
                }
            }
            // writeout chunk of previous tile: 4 rows per K-step
            if (t > 0) {
                #pragma unroll
                for (int rr = 0; rr < 4; rr++) {
                    float v0 = sRowW[0];
                    float v1 = sRowW[32];
                    gRowW[0]  = v0;
                    gRowW[32] = v1;
                    if (lane < 3) gRowW[64] = sRowW[64];
                    sRowW += DS_STRIDE;
                    gRowW += P_TOTAL;
                }
            }
        }
        __syncthreads();   // all Ds reads (writeout t-1) done; compute(t) done

        // ---- Stage d(t) to SMEM with bias folded (float2 stores) ----
        #pragma unroll
        for (int nf = 0; nf < 6; nf++) {
            const int y = cb + nf * 8;   // even
            const float b0 = bias_s[y];
            const float b1 = bias_s[y + 1];
            #pragma unroll
            for (int mf = 0; mf < 2; mf++) {
                const int rA = r0 + mf * 16;
                if (y + 1 < NY) {
                    *(float2*)&Ds[rA * DS_STRIDE + y] =
                        make_float2(d[mf][nf][0] + b0, d[mf][nf][1] + b1);
                    *(float2*)&Ds[(rA + 8) * DS_STRIDE + y] =
                        make_float2(d[mf][nf][2] + b0, d[mf][nf][3] + b1);
                } else if (y < NY) {
                    Ds[rA * DS_STRIDE + y]       = d[mf][nf][0] + b0;
                    Ds[(rA + 8) * DS_STRIDE + y] = d[mf][nf][2] + b0;
                }
            }
        }
        asm volatile("cp.async.wait_group 0;" ::: "memory");   // A[t+1] landed (this thread)
        __syncthreads();   // Ds(t) ready; A[t+1] visible to all
    }

    // ---- Final writeout: last tile ----
    {
        const int btL = by * BT_PER_CTA + BT_PER_CTA - 1;
        float* gRow = out + (size_t)(btL * TILE_M + warp * 16) * P_TOTAL + x * NY + lane;
        const float* sRow = Ds + (warp * 16) * DS_STRIDE + lane;
        #pragma unroll
        for (int rr = 0; rr < 16; rr++) {
            float v0 = sRow[0];
            float v1 = sRow[32];
            gRow[0]  = v0;
            gRow[32] = v1;
            if (lane < 3) gRow[64] = sRow[64];
            sRow += DS_STRIDE;
            gRow += P_TOTAL;
        }
    }
}

// ---------------- Launch ----------------
extern "C" void kernel_launch(void* const* d_in, const int* in_sizes, int n_in,
                              void* d_out, int out_size) {
    const float* inputs = nullptr;  // 8192*64
    const float* W = nullptr;       // 5494*64
    const float* bias = nullptr;    // 5494
    for (int i = 0; i < n_in; i++) {
        if (in_sizes[i] == B_TOTAL * F_DIM) inputs = (const float*)d_in[i];
        else if (in_sizes[i] == P_TOTAL * F_DIM) W = (const float*)d_in[i];
        else if (in_sizes[i] == P_TOTAL) bias = (const float*)d_in[i];
    }
    float* out = (float*)d_out;

    prep_kernel<<<PREP_BLOCKS, 256>>>(inputs);

    cudaFuncSetAttribute(gemm_kernel, cudaFuncAttributeMaxDynamicSharedMemorySize, SMEM_TOTAL);
    dim3 grid(NX, GRID_Y);   // (82, 16)
    gemm_kernel<<<grid, 256, SMEM_TOTAL>>>(W, bias, out);
}